// round 4
// baseline (speedup 1.0000x reference)
#include <cuda_runtime.h>
#include <cuda_fp16.h>

#define NN 50000
#define NE 800000
#define IND 64
#define HD 128
#define OD 64
#define BN_EPS 1e-5f
#define NB 49   // ceil(NN/1024)

typedef unsigned long long ull;

// ---- scratch (__device__ globals; no allocs) ----
__device__ __align__(256) int    g_degi[NN];
__device__ __align__(256) int    g_off[NN + 1];
__device__ __align__(256) int    g_cur[NN];
__device__ __align__(256) int    g_esrc[NE];
__device__ __align__(256) int    g_bsums[NB];
__device__ __align__(256) float  g_deginv[NN];
__device__ __align__(256) __half g_xh[NN * IND];      // fp16 x
__device__ __align__(256) __half g_agg1h[NN * IND];   // fp16 mean-agg of x
__device__ __align__(256) __half g_hpre[NN * HD];     // fp16 pre-BN layer-1 out
__device__ __align__(256) __half g_hrelu[NN * HD];    // fp16 relu(bn(hpre))
__device__ __align__(256) __half g_agg2h[NN * HD];    // fp16 mean-agg of hrelu
__device__ __align__(256) float  g_bnsum[HD];
__device__ __align__(256) float  g_bnsq[HD];
// packed weight pairs: (W[2k][j], W[2k+1][j]) as f32x2
__device__ __align__(256) ull    g_w1l[(IND / 2) * HD];
__device__ __align__(256) ull    g_w1r[(IND / 2) * HD];
__device__ __align__(256) ull    g_w2l[(HD / 2) * OD];
__device__ __align__(256) ull    g_w2r[(HD / 2) * OD];

__device__ __forceinline__ ull pack2(float x, float y) {
    ull r;
    asm("mov.b64 %0, {%1,%2};" : "=l"(r) : "f"(x), "f"(y));
    return r;
}
__device__ __forceinline__ float2 unpack2(ull v) {
    float2 r;
    asm("mov.b64 {%0,%1}, %2;" : "=f"(r.x), "=f"(r.y) : "l"(v));
    return r;
}
__device__ __forceinline__ void ffma2(ull& d, ull a, ull b) {
    asm("fma.rn.f32x2 %0, %1, %2, %0;" : "+l"(d) : "l"(a), "l"(b));
}
__device__ __forceinline__ void h8_to_f8(uint4 u, float* d) {
    float2 f0 = __half22float2(*(__half2*)&u.x);
    float2 f1 = __half22float2(*(__half2*)&u.y);
    float2 f2 = __half22float2(*(__half2*)&u.z);
    float2 f3 = __half22float2(*(__half2*)&u.w);
    d[0] = f0.x; d[1] = f0.y; d[2] = f1.x; d[3] = f1.y;
    d[4] = f2.x; d[5] = f2.y; d[6] = f3.x; d[7] = f3.y;
}
__device__ __forceinline__ uint4 f8_to_h8(const float* s) {
    __half2 a = __floats2half2_rn(s[0], s[1]);
    __half2 b = __floats2half2_rn(s[2], s[3]);
    __half2 c = __floats2half2_rn(s[4], s[5]);
    __half2 d = __floats2half2_rn(s[6], s[7]);
    uint4 u;
    u.x = *(unsigned int*)&a; u.y = *(unsigned int*)&b;
    u.z = *(unsigned int*)&c; u.w = *(unsigned int*)&d;
    return u;
}

// ---- prep: zero counters, pack weights, convert x->fp16 ----
__global__ void k_prep(const float* __restrict__ x,
                       const float* __restrict__ W1l, const float* __restrict__ W1r,
                       const float* __restrict__ W2l, const float* __restrict__ W2r) {
    int t = blockIdx.x * blockDim.x + threadIdx.x;
    int stride = gridDim.x * blockDim.x;
    for (int i = t; i < NN; i += stride) g_degi[i] = 0;
    if (t < HD) { g_bnsum[t] = 0.f; g_bnsq[t] = 0.f; }
    for (int i = t; i < (IND / 2) * HD; i += stride) {
        int kp = i >> 7, j = i & 127;
        g_w1l[i] = pack2(W1l[(2 * kp) * HD + j], W1l[(2 * kp + 1) * HD + j]);
        g_w1r[i] = pack2(W1r[(2 * kp) * HD + j], W1r[(2 * kp + 1) * HD + j]);
    }
    for (int i = t; i < (HD / 2) * OD; i += stride) {
        int kp = i >> 6, j = i & 63;
        g_w2l[i] = pack2(W2l[(2 * kp) * OD + j], W2l[(2 * kp + 1) * OD + j]);
        g_w2r[i] = pack2(W2r[(2 * kp) * OD + j], W2r[(2 * kp + 1) * OD + j]);
    }
    for (int i = t; i < NN * IND / 8; i += stride) {
        float4 v0 = ((const float4*)x)[2 * i];
        float4 v1 = ((const float4*)x)[2 * i + 1];
        float f[8] = {v0.x, v0.y, v0.z, v0.w, v1.x, v1.y, v1.z, v1.w};
        ((uint4*)g_xh)[i] = f8_to_h8(f);
    }
}

// ---- degree histogram, 4 edges/thread ----
__global__ void k_deg(const int* __restrict__ dst) {
    int t = blockIdx.x * blockDim.x + threadIdx.x;
    if (t * 4 >= NE) return;
    int4 d = ((const int4*)dst)[t];
    atomicAdd(&g_degi[d.x], 1);
    atomicAdd(&g_degi[d.y], 1);
    atomicAdd(&g_degi[d.z], 1);
    atomicAdd(&g_degi[d.w], 1);
}

// ---- scan stage 1: per-block exclusive scan + block totals ----
__global__ void k_scan1() {
    __shared__ int ws[32];
    int tid = threadIdx.x, lane = tid & 31, w = tid >> 5;
    int i = blockIdx.x * 1024 + tid;
    int v = (i < NN) ? g_degi[i] : 0;
    int s = v;
#pragma unroll
    for (int o = 1; o < 32; o <<= 1) {
        int tt = __shfl_up_sync(0xffffffffu, s, o);
        if (lane >= o) s += tt;
    }
    if (lane == 31) ws[w] = s;
    __syncthreads();
    if (w == 0) {
        int t2 = ws[lane];
#pragma unroll
        for (int o = 1; o < 32; o <<= 1) {
            int tt = __shfl_up_sync(0xffffffffu, t2, o);
            if (lane >= o) t2 += tt;
        }
        ws[lane] = t2;
    }
    __syncthreads();
    int excl = ((w > 0) ? ws[w - 1] : 0) + s - v;
    if (i < NN) g_off[i] = excl;
    if (tid == 1023) g_bsums[blockIdx.x] = ws[31];
}

// ---- scan stage 2 (fused): every block scans the 49 sums, applies its prefix ----
__global__ void k_scan3() {
    __shared__ int sb[64];
    int tid = threadIdx.x;
    if (tid < 64) {
        int lane = tid & 31;
        int v = (tid < NB) ? g_bsums[tid] : 0;
        int s = v;
#pragma unroll
        for (int o = 1; o < 32; o <<= 1) {
            int tt = __shfl_up_sync(0xffffffffu, s, o);
            if (lane >= o) s += tt;
        }
        sb[tid] = s - v;   // exclusive within warp
    }
    __syncthreads();
    if (tid >= 32 && tid < 64) {
        // add warp0 total (inclusive of element 31)
        int w0tot = sb[31] + ((31 < NB) ? g_bsums[31] : 0);
        sb[tid] += w0tot;
    }
    __syncthreads();
    int pref = sb[blockIdx.x];
    int i = blockIdx.x * 1024 + tid;
    if (i < NN) {
        int off = g_off[i] + pref;
        g_off[i] = off;
        g_cur[i] = off;
        int d = g_degi[i];
        g_deginv[i] = (d > 0) ? (1.0f / (float)d) : 0.0f;
    }
    if (i == NN) g_off[NN] = NE;
}

// ---- CSR fill, 4 edges/thread ----
__global__ void k_fill(const int* __restrict__ src, const int* __restrict__ dst) {
    int t = blockIdx.x * blockDim.x + threadIdx.x;
    if (t * 4 >= NE) return;
    int4 s4 = ((const int4*)src)[t];
    int4 d4 = ((const int4*)dst)[t];
    int p0 = atomicAdd(&g_cur[d4.x], 1);
    int p1 = atomicAdd(&g_cur[d4.y], 1);
    int p2 = atomicAdd(&g_cur[d4.z], 1);
    int p3 = atomicAdd(&g_cur[d4.w], 1);
    g_esrc[p0] = s4.x;
    g_esrc[p1] = s4.y;
    g_esrc[p2] = s4.z;
    g_esrc[p3] = s4.w;
}

// ---- layer-1 mean aggregation: 8 threads/node, fp16 in/out ----
__global__ void k_agg1() {
    int t = blockIdx.x * blockDim.x + threadIdx.x;
    int node = t >> 3, c = t & 7;
    if (node >= NN) return;
    int beg = g_off[node], end = g_off[node + 1];
    float a[8] = {0.f, 0.f, 0.f, 0.f, 0.f, 0.f, 0.f, 0.f};
    for (int j = beg; j < end; j++) {
        int s = g_esrc[j];
        float f[8];
        h8_to_f8(((const uint4*)g_xh)[s * 8 + c], f);
#pragma unroll
        for (int q = 0; q < 8; q++) a[q] += f[q];
    }
    float di = g_deginv[node];
#pragma unroll
    for (int q = 0; q < 8; q++) a[q] *= di;
    ((uint4*)g_agg1h)[node * 8 + c] = f8_to_h8(a);
}

// ---- layer-1 dense (FFMA2): h_pre = agg1@W1l + b1 + x@W1r ; BN partials ----
#define NT1 64
__global__ void __launch_bounds__(512) k_lin1(const float* __restrict__ b1) {
    __shared__ float sa[NT1][IND];
    __shared__ float sx[NT1][IND];
    const int n0 = blockIdx.x * NT1;
    const int tid = threadIdx.x;   // 512

    // tile load: 2 arrays x 64 rows x 8 uint4 = 1024 loads
    for (int idx = tid; idx < 1024; idx += 512) {
        int arr = idx >> 9;
        int e = idx & 511;
        int r = e >> 3, c = e & 7;
        int node = n0 + r;
        uint4 u = make_uint4(0u, 0u, 0u, 0u);
        if (node < NN)
            u = (arr == 0) ? ((const uint4*)g_agg1h)[node * 8 + c]
                           : ((const uint4*)g_xh)[node * 8 + c];
        float f[8];
        h8_to_f8(u, f);
        float* dp = (arr == 0) ? &sa[r][8 * c] : &sx[r][8 * c];
#pragma unroll
        for (int q = 0; q < 8; q++) dp[q] = f[q];
    }
    __syncthreads();

    const int j = tid & 127;
    const int bn = (tid >> 7) * 16;   // node group of 16
    ull acc[16];
#pragma unroll
    for (int n = 0; n < 16; n++) acc[n] = 0ull;

    for (int kq = 0; kq < IND / 4; kq++) {
        ull wl01 = g_w1l[(2 * kq) * HD + j];
        ull wl23 = g_w1l[(2 * kq + 1) * HD + j];
        ull wr01 = g_w1r[(2 * kq) * HD + j];
        ull wr23 = g_w1r[(2 * kq + 1) * HD + j];
#pragma unroll
        for (int n = 0; n < 16; n++) {
            ulonglong2 a = *(const ulonglong2*)&sa[bn + n][4 * kq];
            ulonglong2 xx = *(const ulonglong2*)&sx[bn + n][4 * kq];
            ffma2(acc[n], a.x, wl01);
            ffma2(acc[n], a.y, wl23);
            ffma2(acc[n], xx.x, wr01);
            ffma2(acc[n], xx.y, wr23);
        }
    }

    const float bj = b1[j];
    float s = 0.f, sq = 0.f;
#pragma unroll
    for (int n = 0; n < 16; n++) {
        int node = n0 + bn + n;
        if (node < NN) {
            float2 p = unpack2(acc[n]);
            float v = p.x + p.y + bj;
            g_hpre[node * HD + j] = __float2half_rn(v);
            s += v;
            sq += v * v;
        }
    }
    atomicAdd(&g_bnsum[j], s);
    atomicAdd(&g_bnsq[j], sq);
}

// ---- BN finalize + relu, fused: g_hrelu = fp16(relu(bn(hpre))) ----
__global__ void k_hrelu(const float* __restrict__ gamma,
                        const float* __restrict__ beta) {
    __shared__ float s_sc[HD];
    __shared__ float s_sh[HD];
    int tid = threadIdx.x;
    if (tid < HD) {
        float mu = g_bnsum[tid] * (1.0f / NN);
        float var = g_bnsq[tid] * (1.0f / NN) - mu * mu;
        float sc = gamma[tid] * rsqrtf(var + BN_EPS);
        s_sc[tid] = sc;
        s_sh[tid] = beta[tid] - mu * sc;
    }
    __syncthreads();
    int i = blockIdx.x * blockDim.x + tid;   // over NN*HD/8 uint4s
    if (i >= NN * HD / 8) return;
    int c = i & 15;              // feature group: features 8c..8c+7
    float f[8];
    h8_to_f8(((const uint4*)g_hpre)[i], f);
#pragma unroll
    for (int q = 0; q < 8; q++)
        f[q] = fmaxf(fmaf(f[q], s_sc[8 * c + q], s_sh[8 * c + q]), 0.f);
    ((uint4*)g_hrelu)[i] = f8_to_h8(f);
}

// ---- layer-2 mean aggregation: 16 threads/node, fp16 in/out ----
__global__ void k_agg2() {
    int t = blockIdx.x * blockDim.x + threadIdx.x;
    int node = t >> 4, c = t & 15;
    if (node >= NN) return;
    int beg = g_off[node], end = g_off[node + 1];
    float a[8] = {0.f, 0.f, 0.f, 0.f, 0.f, 0.f, 0.f, 0.f};
    for (int j = beg; j < end; j++) {
        int s = g_esrc[j];
        float f[8];
        h8_to_f8(((const uint4*)g_hrelu)[s * 16 + c], f);
#pragma unroll
        for (int q = 0; q < 8; q++) a[q] += f[q];
    }
    float di = g_deginv[node];
#pragma unroll
    for (int q = 0; q < 8; q++) a[q] *= di;
    ((uint4*)g_agg2h)[node * 16 + c] = f8_to_h8(a);
}

// ---- layer-2 dense (FFMA2): out = agg2@W2l + b2 + hrelu@W2r ----
#define NT2 64
__global__ void __launch_bounds__(256) k_lin2(const float* __restrict__ b2,
                                              float* __restrict__ out) {
    __shared__ float sg[NT2][HD];
    __shared__ float sh_[NT2][HD];
    const int n0 = blockIdx.x * NT2;
    const int tid = threadIdx.x;   // 256

    // tile load: 2 arrays x 64 rows x 16 uint4 = 2048 loads
    for (int idx = tid; idx < 2048; idx += 256) {
        int arr = idx >> 10;
        int e = idx & 1023;
        int r = e >> 4, c = e & 15;
        int node = n0 + r;
        uint4 u = make_uint4(0u, 0u, 0u, 0u);
        if (node < NN)
            u = (arr == 0) ? ((const uint4*)g_agg2h)[node * 16 + c]
                           : ((const uint4*)g_hrelu)[node * 16 + c];
        float f[8];
        h8_to_f8(u, f);
        float* dp = (arr == 0) ? &sg[r][8 * c] : &sh_[r][8 * c];
#pragma unroll
        for (int q = 0; q < 8; q++) dp[q] = f[q];
    }
    __syncthreads();

    const int j = tid & 63;
    const int bn = (tid >> 6) * 16;   // node group of 16
    ull acc[16];
#pragma unroll
    for (int n = 0; n < 16; n++) acc[n] = 0ull;

    for (int kq = 0; kq < HD / 4; kq++) {
        ull wl01 = g_w2l[(2 * kq) * OD + j];
        ull wl23 = g_w2l[(2 * kq + 1) * OD + j];
        ull wr01 = g_w2r[(2 * kq) * OD + j];
        ull wr23 = g_w2r[(2 * kq + 1) * OD + j];
#pragma unroll
        for (int n = 0; n < 16; n++) {
            ulonglong2 a = *(const ulonglong2*)&sg[bn + n][4 * kq];
            ulonglong2 h = *(const ulonglong2*)&sh_[bn + n][4 * kq];
            ffma2(acc[n], a.x, wl01);
            ffma2(acc[n], a.y, wl23);
            ffma2(acc[n], h.x, wr01);
            ffma2(acc[n], h.y, wr23);
        }
    }

    const float bj = b2[j];
#pragma unroll
    for (int n = 0; n < 16; n++) {
        int node = n0 + bn + n;
        if (node < NN) {
            float2 p = unpack2(acc[n]);
            out[node * OD + j] = p.x + p.y + bj;
        }
    }
}

extern "C" void kernel_launch(void* const* d_in, const int* in_sizes, int n_in,
                              void* d_out, int out_size) {
    const float* x     = (const float*)d_in[0];
    const int*   ei    = (const int*)d_in[1];
    const float* W1l   = (const float*)d_in[2];
    const float* b1    = (const float*)d_in[3];
    const float* W1r   = (const float*)d_in[4];
    const float* gamma = (const float*)d_in[5];
    const float* beta  = (const float*)d_in[6];
    const float* W2l   = (const float*)d_in[7];
    const float* b2    = (const float*)d_in[8];
    const float* W2r   = (const float*)d_in[9];
    float* out = (float*)d_out;

    const int* src = ei;
    const int* dst = ei + NE;

    k_prep<<<2048, 256>>>(x, W1l, W1r, W2l, W2r);
    k_deg<<<(NE / 4 + 255) / 256, 256>>>(dst);
    k_scan1<<<NB, 1024>>>();
    k_scan3<<<NB, 1024>>>();
    k_fill<<<(NE / 4 + 255) / 256, 256>>>(src, dst);
    k_agg1<<<(NN * 8 + 255) / 256, 256>>>();
    k_lin1<<<(NN + NT1 - 1) / NT1, 512>>>(b1);
    k_hrelu<<<(NN * HD / 8 + 255) / 256, 256>>>(gamma, beta);
    k_agg2<<<(NN * 16 + 255) / 256, 256>>>();
    k_lin2<<<(NN + NT2 - 1) / NT2, 256>>>(b2, out);
}

// round 5
// speedup vs baseline: 1.0459x; 1.0459x over previous
#include <cuda_runtime.h>
#include <cuda_fp16.h>

#define NN 50000
#define NE 800000
#define IND 64
#define HD 128
#define OD 64
#define BN_EPS 1e-5f
#define NB 49   // ceil(NN/1024)

typedef unsigned long long ull;

// ---- scratch (__device__ globals; zero-initialized at load; we preserve
//      the zero-invariant on g_degi / g_bnsum / g_bnsq across calls) ----
__device__ __align__(256) int    g_degi[NN];        // zero-invariant
__device__ __align__(256) int    g_off[NN + 1];
__device__ __align__(256) int    g_cur[NN];
__device__ __align__(256) int    g_esrc[NE];
__device__ __align__(256) int    g_bsums[NB];
__device__ __align__(256) float  g_deginv[NN];
__device__ __align__(256) __half g_xh[NN * IND];    // fp16 x (gather side)
__device__ __align__(256) float  g_agg1[NN * IND];  // fp32 mean-agg of x
__device__ __align__(256) float  g_hpre[NN * HD];   // fp32 pre-BN layer-1 out
__device__ __align__(256) __half g_hrelu[NN * HD];  // fp16 relu(bn(hpre)) (gather side)
__device__ __align__(256) float  g_agg2[NN * HD];   // fp32 mean-agg of hrelu
__device__ __align__(256) float  g_bnsum[HD];       // zero-invariant
__device__ __align__(256) float  g_bnsq[HD];        // zero-invariant
__device__ __align__(256) float  g_scale[HD];
__device__ __align__(256) float  g_shift[HD];
// packed weight pairs: (W[2k][j], W[2k+1][j]) as f32x2
__device__ __align__(256) ull    g_w1l[(IND / 2) * HD];
__device__ __align__(256) ull    g_w1r[(IND / 2) * HD];
__device__ __align__(256) ull    g_w2l[(HD / 2) * OD];
__device__ __align__(256) ull    g_w2r[(HD / 2) * OD];

__device__ __forceinline__ ull pack2(float x, float y) {
    ull r;
    asm("mov.b64 %0, {%1,%2};" : "=l"(r) : "f"(x), "f"(y));
    return r;
}
__device__ __forceinline__ float2 unpack2(ull v) {
    float2 r;
    asm("mov.b64 {%0,%1}, %2;" : "=f"(r.x), "=f"(r.y) : "l"(v));
    return r;
}
__device__ __forceinline__ void ffma2(ull& d, ull a, ull b) {
    asm("fma.rn.f32x2 %0, %1, %2, %0;" : "+l"(d) : "l"(a), "l"(b));
}
__device__ __forceinline__ void h8_to_f8(uint4 u, float* d) {
    float2 f0 = __half22float2(*(__half2*)&u.x);
    float2 f1 = __half22float2(*(__half2*)&u.y);
    float2 f2 = __half22float2(*(__half2*)&u.z);
    float2 f3 = __half22float2(*(__half2*)&u.w);
    d[0] = f0.x; d[1] = f0.y; d[2] = f1.x; d[3] = f1.y;
    d[4] = f2.x; d[5] = f2.y; d[6] = f3.x; d[7] = f3.y;
}
__device__ __forceinline__ uint4 f8_to_h8(const float* s) {
    __half2 a = __floats2half2_rn(s[0], s[1]);
    __half2 b = __floats2half2_rn(s[2], s[3]);
    __half2 c = __floats2half2_rn(s[4], s[5]);
    __half2 d = __floats2half2_rn(s[6], s[7]);
    uint4 u;
    u.x = *(unsigned int*)&a; u.y = *(unsigned int*)&b;
    u.z = *(unsigned int*)&c; u.w = *(unsigned int*)&d;
    return u;
}

// ---- fused prep + degree histogram (g_degi is already zero on entry) ----
__global__ void k_prepdeg(const float* __restrict__ x,
                          const float* __restrict__ W1l, const float* __restrict__ W1r,
                          const float* __restrict__ W2l, const float* __restrict__ W2r,
                          const int* __restrict__ dst) {
    int t = blockIdx.x * blockDim.x + threadIdx.x;
    int stride = gridDim.x * blockDim.x;
    for (int i = t; i < (IND / 2) * HD; i += stride) {
        int kp = i >> 7, j = i & 127;
        g_w1l[i] = pack2(W1l[(2 * kp) * HD + j], W1l[(2 * kp + 1) * HD + j]);
        g_w1r[i] = pack2(W1r[(2 * kp) * HD + j], W1r[(2 * kp + 1) * HD + j]);
    }
    for (int i = t; i < (HD / 2) * OD; i += stride) {
        int kp = i >> 6, j = i & 63;
        g_w2l[i] = pack2(W2l[(2 * kp) * OD + j], W2l[(2 * kp + 1) * OD + j]);
        g_w2r[i] = pack2(W2r[(2 * kp) * OD + j], W2r[(2 * kp + 1) * OD + j]);
    }
    for (int i = t; i < NN * IND / 8; i += stride) {
        float4 v0 = ((const float4*)x)[2 * i];
        float4 v1 = ((const float4*)x)[2 * i + 1];
        float f[8] = {v0.x, v0.y, v0.z, v0.w, v1.x, v1.y, v1.z, v1.w};
        ((uint4*)g_xh)[i] = f8_to_h8(f);
    }
    for (int i = t; i < NE / 4; i += stride) {
        int4 d = ((const int4*)dst)[i];
        atomicAdd(&g_degi[d.x], 1);
        atomicAdd(&g_degi[d.y], 1);
        atomicAdd(&g_degi[d.z], 1);
        atomicAdd(&g_degi[d.w], 1);
    }
}

// ---- scan stage 1: per-block exclusive scan + block totals ----
__global__ void k_scan1() {
    __shared__ int ws[32];
    int tid = threadIdx.x, lane = tid & 31, w = tid >> 5;
    int i = blockIdx.x * 1024 + tid;
    int v = (i < NN) ? g_degi[i] : 0;
    int s = v;
#pragma unroll
    for (int o = 1; o < 32; o <<= 1) {
        int tt = __shfl_up_sync(0xffffffffu, s, o);
        if (lane >= o) s += tt;
    }
    if (lane == 31) ws[w] = s;
    __syncthreads();
    if (w == 0) {
        int t2 = ws[lane];
#pragma unroll
        for (int o = 1; o < 32; o <<= 1) {
            int tt = __shfl_up_sync(0xffffffffu, t2, o);
            if (lane >= o) t2 += tt;
        }
        ws[lane] = t2;
    }
    __syncthreads();
    int excl = ((w > 0) ? ws[w - 1] : 0) + s - v;
    if (i < NN) g_off[i] = excl;
    if (tid == 1023) g_bsums[blockIdx.x] = ws[31];
}

// ---- scan stage 2 (fused): scan 49 block sums, apply prefix, deginv,
//      and restore the g_degi zero-invariant ----
__global__ void k_scan3() {
    __shared__ int sb[64];
    int tid = threadIdx.x;
    if (tid < 64) {
        int lane = tid & 31;
        int v = (tid < NB) ? g_bsums[tid] : 0;
        int s = v;
#pragma unroll
        for (int o = 1; o < 32; o <<= 1) {
            int tt = __shfl_up_sync(0xffffffffu, s, o);
            if (lane >= o) s += tt;
        }
        sb[tid] = s - v;   // exclusive within warp
    }
    __syncthreads();
    if (tid >= 32 && tid < 64) {
        int w0tot = sb[31] + g_bsums[31];
        sb[tid] += w0tot;
    }
    __syncthreads();
    int pref = sb[blockIdx.x];
    int i = blockIdx.x * 1024 + tid;
    if (i < NN) {
        int off = g_off[i] + pref;
        g_off[i] = off;
        g_cur[i] = off;
        int d = g_degi[i];
        g_deginv[i] = (d > 0) ? (1.0f / (float)d) : 0.0f;
        g_degi[i] = 0;   // zero-invariant for next call
    }
    if (i == NN) g_off[NN] = NE;
}

// ---- CSR fill, 8 edges/thread ----
__global__ void k_fill(const int* __restrict__ src, const int* __restrict__ dst) {
    int t = blockIdx.x * blockDim.x + threadIdx.x;
    if (t * 8 >= NE) return;
    int4 s0 = ((const int4*)src)[2 * t];
    int4 s1 = ((const int4*)src)[2 * t + 1];
    int4 d0 = ((const int4*)dst)[2 * t];
    int4 d1 = ((const int4*)dst)[2 * t + 1];
    int p0 = atomicAdd(&g_cur[d0.x], 1);
    int p1 = atomicAdd(&g_cur[d0.y], 1);
    int p2 = atomicAdd(&g_cur[d0.z], 1);
    int p3 = atomicAdd(&g_cur[d0.w], 1);
    int p4 = atomicAdd(&g_cur[d1.x], 1);
    int p5 = atomicAdd(&g_cur[d1.y], 1);
    int p6 = atomicAdd(&g_cur[d1.z], 1);
    int p7 = atomicAdd(&g_cur[d1.w], 1);
    g_esrc[p0] = s0.x;
    g_esrc[p1] = s0.y;
    g_esrc[p2] = s0.z;
    g_esrc[p3] = s0.w;
    g_esrc[p4] = s1.x;
    g_esrc[p5] = s1.y;
    g_esrc[p6] = s1.z;
    g_esrc[p7] = s1.w;
}

// ---- layer-1 mean aggregation: 8 threads/node, fp16 gather, fp32 out ----
__global__ void k_agg1() {
    int t = blockIdx.x * blockDim.x + threadIdx.x;
    int node = t >> 3, c = t & 7;
    if (node >= NN) return;
    int beg = g_off[node], end = g_off[node + 1];
    float a[8] = {0.f, 0.f, 0.f, 0.f, 0.f, 0.f, 0.f, 0.f};
    for (int j = beg; j < end; j++) {
        int s = g_esrc[j];
        float f[8];
        h8_to_f8(((const uint4*)g_xh)[s * 8 + c], f);
#pragma unroll
        for (int q = 0; q < 8; q++) a[q] += f[q];
    }
    float di = g_deginv[node];
#pragma unroll
    for (int q = 0; q < 8; q++) a[q] *= di;
    float4 o0 = make_float4(a[0], a[1], a[2], a[3]);
    float4 o1 = make_float4(a[4], a[5], a[6], a[7]);
    ((float4*)g_agg1)[node * (IND / 4) + c * 2 + 0] = o0;
    ((float4*)g_agg1)[node * (IND / 4) + c * 2 + 1] = o1;
}

// ---- layer-1 dense (FFMA2): h_pre = agg1@W1l + b1 + x@W1r ; BN partials ----
#define NT1 32
__global__ void __launch_bounds__(128) k_lin1(const float* __restrict__ x,
                                              const float* __restrict__ b1) {
    __shared__ float sa[NT1][IND];
    __shared__ float sx[NT1][IND];
    const int n0 = blockIdx.x * NT1;
    const int tid = threadIdx.x;   // 128

    for (int idx = tid; idx < NT1 * (IND / 4); idx += 128) {
        int r = idx >> 4, c = idx & 15;
        int node = n0 + r;
        float4 va = make_float4(0.f, 0.f, 0.f, 0.f), vx = va;
        if (node < NN) {
            va = ((const float4*)g_agg1)[node * 16 + c];
            vx = ((const float4*)x)[node * 16 + c];
        }
        *(float4*)&sa[r][4 * c] = va;
        *(float4*)&sx[r][4 * c] = vx;
    }
    __syncthreads();

    const int j = tid;   // 0..127
    ull acc[NT1];
#pragma unroll
    for (int n = 0; n < NT1; n++) acc[n] = 0ull;

    for (int kq = 0; kq < IND / 4; kq++) {
        ull wl01 = g_w1l[(2 * kq) * HD + j];
        ull wl23 = g_w1l[(2 * kq + 1) * HD + j];
        ull wr01 = g_w1r[(2 * kq) * HD + j];
        ull wr23 = g_w1r[(2 * kq + 1) * HD + j];
#pragma unroll
        for (int n = 0; n < NT1; n++) {
            ulonglong2 a = *(const ulonglong2*)&sa[n][4 * kq];
            ulonglong2 xx = *(const ulonglong2*)&sx[n][4 * kq];
            ffma2(acc[n], a.x, wl01);
            ffma2(acc[n], a.y, wl23);
            ffma2(acc[n], xx.x, wr01);
            ffma2(acc[n], xx.y, wr23);
        }
    }

    const float bj = b1[j];
    float s = 0.f, sq = 0.f;
#pragma unroll
    for (int n = 0; n < NT1; n++) {
        int node = n0 + n;
        if (node < NN) {
            float2 p = unpack2(acc[n]);
            float v = p.x + p.y + bj;
            g_hpre[node * HD + j] = v;
            s += v;
            sq += v * v;
        }
    }
    atomicAdd(&g_bnsum[j], s);
    atomicAdd(&g_bnsq[j], sq);
}

// ---- BN finalize + relu, fused: g_hrelu = fp16(relu(bn(hpre))) ----
__global__ void k_hrelu(const float* __restrict__ gamma,
                        const float* __restrict__ beta) {
    __shared__ float s_sc[HD];
    __shared__ float s_sh[HD];
    int tid = threadIdx.x;
    if (tid < HD) {
        float mu = g_bnsum[tid] * (1.0f / NN);
        float var = g_bnsq[tid] * (1.0f / NN) - mu * mu;
        float sc = gamma[tid] * rsqrtf(var + BN_EPS);
        float sh = beta[tid] - mu * sc;
        s_sc[tid] = sc;
        s_sh[tid] = sh;
        if (blockIdx.x == 0) { g_scale[tid] = sc; g_shift[tid] = sh; }
    }
    __syncthreads();
    int i = blockIdx.x * blockDim.x + tid;   // over NN*HD/4 float4s
    if (i >= NN * HD / 4) return;
    int c = i & 31;              // feature group: features 4c..4c+3
    float4 h = ((const float4*)g_hpre)[i];
    float4 sc = *(const float4*)&s_sc[4 * c];
    float4 sh = *(const float4*)&s_sh[4 * c];
    float v0 = fmaxf(fmaf(h.x, sc.x, sh.x), 0.f);
    float v1 = fmaxf(fmaf(h.y, sc.y, sh.y), 0.f);
    float v2 = fmaxf(fmaf(h.z, sc.z, sh.z), 0.f);
    float v3 = fmaxf(fmaf(h.w, sc.w, sh.w), 0.f);
    __half2 a = __floats2half2_rn(v0, v1);
    __half2 b = __floats2half2_rn(v2, v3);
    uint2 u;
    u.x = *(unsigned int*)&a;
    u.y = *(unsigned int*)&b;
    ((uint2*)g_hrelu)[i] = u;
}

// ---- layer-2 mean aggregation: 16 threads/node, fp16 gather, fp32 out;
//      also restores g_bnsum/g_bnsq zero-invariant ----
__global__ void k_agg2() {
    int t = blockIdx.x * blockDim.x + threadIdx.x;
    if (t < HD) { g_bnsum[t] = 0.f; g_bnsq[t] = 0.f; }
    int node = t >> 4, c = t & 15;
    if (node >= NN) return;
    int beg = g_off[node], end = g_off[node + 1];
    float a[8] = {0.f, 0.f, 0.f, 0.f, 0.f, 0.f, 0.f, 0.f};
    for (int j = beg; j < end; j++) {
        int s = g_esrc[j];
        float f[8];
        h8_to_f8(((const uint4*)g_hrelu)[s * 16 + c], f);
#pragma unroll
        for (int q = 0; q < 8; q++) a[q] += f[q];
    }
    float di = g_deginv[node];
#pragma unroll
    for (int q = 0; q < 8; q++) a[q] *= di;
    float4 o0 = make_float4(a[0], a[1], a[2], a[3]);
    float4 o1 = make_float4(a[4], a[5], a[6], a[7]);
    ((float4*)g_agg2)[node * (HD / 4) + c * 2 + 0] = o0;
    ((float4*)g_agg2)[node * (HD / 4) + c * 2 + 1] = o1;
}

// ---- layer-2 dense (FFMA2): out = agg2@W2l + b2 + relu(bn(hpre))@W2r ----
#define NT2 32
__global__ void __launch_bounds__(64) k_lin2(const float* __restrict__ b2,
                                             float* __restrict__ out) {
    __shared__ float sg[NT2][HD];
    __shared__ float sh_[NT2][HD];
    const int n0 = blockIdx.x * NT2;
    const int tid = threadIdx.x;   // 64

    for (int idx = tid; idx < NT2 * (HD / 4); idx += 64) {
        int r = idx >> 5, c = idx & 31;
        int node = n0 + r;
        float4 vg = make_float4(0.f, 0.f, 0.f, 0.f), vh = vg;
        if (node < NN) {
            vg = ((const float4*)g_agg2)[node * 32 + c];
            float4 h  = ((const float4*)g_hpre)[node * 32 + c];
            float4 sc = ((const float4*)g_scale)[c];
            float4 sf = ((const float4*)g_shift)[c];
            vh.x = fmaxf(fmaf(h.x, sc.x, sf.x), 0.f);
            vh.y = fmaxf(fmaf(h.y, sc.y, sf.y), 0.f);
            vh.z = fmaxf(fmaf(h.z, sc.z, sf.z), 0.f);
            vh.w = fmaxf(fmaf(h.w, sc.w, sf.w), 0.f);
        }
        *(float4*)&sg[r][4 * c] = vg;
        *(float4*)&sh_[r][4 * c] = vh;
    }
    __syncthreads();

    const int j = tid;   // 0..63
    ull acc[NT2];
#pragma unroll
    for (int n = 0; n < NT2; n++) acc[n] = 0ull;

    for (int kq = 0; kq < HD / 4; kq++) {
        ull wl01 = g_w2l[(2 * kq) * OD + j];
        ull wl23 = g_w2l[(2 * kq + 1) * OD + j];
        ull wr01 = g_w2r[(2 * kq) * OD + j];
        ull wr23 = g_w2r[(2 * kq + 1) * OD + j];
#pragma unroll
        for (int n = 0; n < NT2; n++) {
            ulonglong2 a = *(const ulonglong2*)&sg[n][4 * kq];
            ulonglong2 h = *(const ulonglong2*)&sh_[n][4 * kq];
            ffma2(acc[n], a.x, wl01);
            ffma2(acc[n], a.y, wl23);
            ffma2(acc[n], h.x, wr01);
            ffma2(acc[n], h.y, wr23);
        }
    }

    const float bj = b2[j];
#pragma unroll
    for (int n = 0; n < NT2; n++) {
        int node = n0 + n;
        if (node < NN) {
            float2 p = unpack2(acc[n]);
            out[node * OD + j] = p.x + p.y + bj;
        }
    }
}

extern "C" void kernel_launch(void* const* d_in, const int* in_sizes, int n_in,
                              void* d_out, int out_size) {
    const float* x     = (const float*)d_in[0];
    const int*   ei    = (const int*)d_in[1];
    const float* W1l   = (const float*)d_in[2];
    const float* b1    = (const float*)d_in[3];
    const float* W1r   = (const float*)d_in[4];
    const float* gamma = (const float*)d_in[5];
    const float* beta  = (const float*)d_in[6];
    const float* W2l   = (const float*)d_in[7];
    const float* b2    = (const float*)d_in[8];
    const float* W2r   = (const float*)d_in[9];
    float* out = (float*)d_out;

    const int* src = ei;
    const int* dst = ei + NE;

    k_prepdeg<<<2048, 256>>>(x, W1l, W1r, W2l, W2r, dst);
    k_scan1<<<NB, 1024>>>();
    k_scan3<<<NB, 1024>>>();
    k_fill<<<(NE / 8 + 255) / 256, 256>>>(src, dst);
    k_agg1<<<(NN * 8 + 255) / 256, 256>>>();
    k_lin1<<<(NN + NT1 - 1) / NT1, 128>>>(x, b1);
    k_hrelu<<<(NN * HD / 4 + 255) / 256, 256>>>(gamma, beta);
    k_agg2<<<(NN * 16 + 255) / 256, 256>>>();
    k_lin2<<<(NN + NT2 - 1) / NT2, 64>>>(b2, out);
}